// round 17
// baseline (speedup 1.0000x reference)
#include <cuda_runtime.h>
#include <cuda_fp16.h>
#include <mma.h>
#include <math.h>
#include <stdint.h>
#include <cstdint>
using namespace nvcuda;

#define EPSV 1e-5f
#define LOG2E 1.44269504088896f

// ---------------- scratch ----------------
__device__ __half g_xh[512 * 4096];     // fp16 x, [c][s]
__device__ __half g_ch[512 * 4096];     // fp16 context, [c][s]
__device__ __half g_wqh[512 * 512];
__device__ float  g_bq[512];
__device__ __half g_wkvh[1024 * 512];
__device__ float  g_bkv[1024];
__device__ __half g_wph[512 * 512];
__device__ __half g_qth[4096 * 512];    // [s][c]
__device__ __half g_kvth[4096 * 1024];  // [s][2c]
__device__ __half g_oth[512 * 4096];    // [c][s]
__device__ float2 g_part[1024];

// ---------------- PTX helpers ----------------
__device__ __forceinline__ uint32_t cvta_s(const void* p) {
    return (uint32_t)__cvta_generic_to_shared(p);
}
__device__ __forceinline__ void ldm_x4(uint32_t& r0, uint32_t& r1, uint32_t& r2, uint32_t& r3,
                                       uint32_t addr) {
    asm volatile("ldmatrix.sync.aligned.m8n8.x4.shared.b16 {%0,%1,%2,%3},[%4];"
                 : "=r"(r0), "=r"(r1), "=r"(r2), "=r"(r3) : "r"(addr));
}
__device__ __forceinline__ void ldm_x4_t(uint32_t& r0, uint32_t& r1, uint32_t& r2, uint32_t& r3,
                                         uint32_t addr) {
    asm volatile("ldmatrix.sync.aligned.m8n8.x4.trans.shared.b16 {%0,%1,%2,%3},[%4];"
                 : "=r"(r0), "=r"(r1), "=r"(r2), "=r"(r3) : "r"(addr));
}
__device__ __forceinline__ void mma16816(float* c, uint32_t a0, uint32_t a1, uint32_t a2,
                                         uint32_t a3, uint32_t b0, uint32_t b1) {
    asm volatile("mma.sync.aligned.m16n8k16.row.col.f32.f16.f16.f32 "
                 "{%0,%1,%2,%3},{%4,%5,%6,%7},{%8,%9},{%0,%1,%2,%3};"
                 : "+f"(c[0]), "+f"(c[1]), "+f"(c[2]), "+f"(c[3])
                 : "r"(a0), "r"(a1), "r"(a2), "r"(a3), "r"(b0), "r"(b1));
}
__device__ __forceinline__ uint32_t packh2(float a, float b) {
    half2 h = __floats2half2_rn(a, b);
    return *(uint32_t*)&h;
}
__device__ __forceinline__ uint32_t clamp_ex2_h2(uint32_t a) {
    uint32_t m, r;
    asm("min.f16x2 %0, %1, %2;" : "=r"(m) : "r"(a), "r"(0x4BC04BC0u));  // clamp 15.5
    asm("ex2.approx.f16x2 %0, %1;" : "=r"(r) : "r"(m));
    return r;
}
__device__ __forceinline__ void cp16(uint32_t saddr, const void* gptr) {
    asm volatile("cp.async.cg.shared.global [%0], [%1], 16;" :: "r"(saddr), "l"(gptr));
}
#define CP_COMMIT()  asm volatile("cp.async.commit_group;")
#define CP_WAIT(N)   asm volatile("cp.async.wait_group %0;" :: "n"(N))

// ---------------- stats: partial sums + fp16 conversion (1024 blocks) ----------------
__global__ void stats_part(const float* __restrict__ x, const float* __restrict__ ctx) {
    int b = blockIdx.x;
    int tg = b >> 6, ch = b & 63;
    int t = tg >> 3, g = tg & 7;
    const int base = g * 64 * 4096 + ch * 4096;
    const float4* p = (const float4*)((t ? ctx : x) + base);
    __half* hdst = (t ? g_ch : g_xh) + base;
    float s1 = 0.f, s2 = 0.f;
    #pragma unroll
    for (int i = threadIdx.x; i < 1024; i += 256) {
        float4 v = p[i];
        s1 += (v.x + v.y) + (v.z + v.w);
        s2 += (v.x * v.x + v.y * v.y) + (v.z * v.z + v.w * v.w);
        half2* d = (half2*)&hdst[i * 4];
        d[0] = __floats2half2_rn(v.x, v.y);
        d[1] = __floats2half2_rn(v.z, v.w);
    }
    __shared__ float sh1[256], sh2[256];
    sh1[threadIdx.x] = s1; sh2[threadIdx.x] = s2;
    __syncthreads();
    for (int o = 128; o > 0; o >>= 1) {
        if (threadIdx.x < o) {
            sh1[threadIdx.x] += sh1[threadIdx.x + o];
            sh2[threadIdx.x] += sh2[threadIdx.x + o];
        }
        __syncthreads();
    }
    if (threadIdx.x == 0) g_part[b] = make_float2(sh1[0], sh2[0]);
}

// ---------------- fold: finalize group stats + fold affine into fp16 weights ----------------
__global__ void fold_kernel(const float* __restrict__ qw, const float* __restrict__ qb,
                            const float* __restrict__ kvw, const float* __restrict__ kvb,
                            const float* __restrict__ pw,
                            const float* __restrict__ nwx, const float* __restrict__ nbx,
                            const float* __restrict__ nwc, const float* __restrict__ nbc) {
    int row = blockIdx.x;
    if (row >= 1536) {
        int r = row - 1536;
        for (int c = threadIdx.x; c < 512; c += 128)
            g_wph[r * 512 + c] = __float2half(pw[r * 512 + c]);
        return;
    }
    __shared__ float mu_s[16], rs_s[16];
    if (threadIdx.x < 16) {
        float s1 = 0.f, s2 = 0.f;
        for (int i = 0; i < 64; ++i) {
            float2 v = g_part[threadIdx.x * 64 + i];
            s1 += v.x; s2 += v.y;
        }
        float n = 64.f * 4096.f;
        float mu = s1 / n;
        float var = fmaxf(s2 / n - mu * mu, 0.f);
        mu_s[threadIdx.x] = mu;
        rs_s[threadIdx.x] = rsqrtf(var + EPSV);
    }
    __syncthreads();

    const float* wsrc; __half* wdst; const float* nw; const float* nb;
    float bias0; float* bdst; float post; int goff;
    if (row < 512) {
        wsrc = qw + row * 512;  wdst = g_wqh + row * 512;
        nw = nwx; nb = nbx; bias0 = qb[row]; bdst = g_bq + row;
        post = 0.125f * LOG2E; goff = 0;
    } else {
        int r = row - 512;
        wsrc = kvw + r * 512;   wdst = g_wkvh + r * 512;
        nw = nwc; nb = nbc; bias0 = kvb[r]; bdst = g_bkv + r; post = 1.f; goff = 8;
    }
    float acc = 0.f;
    for (int c = threadIdx.x; c < 512; c += 128) {
        int gi = goff + (c >> 6);
        float rs = rs_s[gi], mu = mu_s[gi];
        float wn = nw[c];
        float a  = wn * rs;
        float bb = nb[c] - mu * rs * wn;
        float w = wsrc[c];
        wdst[c] = __float2half(w * a * post);
        acc += w * bb;
    }
    __shared__ float sh[128];
    sh[threadIdx.x] = acc;
    __syncthreads();
    for (int o = 64; o > 0; o >>= 1) {
        if (threadIdx.x < o) sh[threadIdx.x] += sh[threadIdx.x + o];
        __syncthreads();
    }
    if (threadIdx.x == 0) *bdst = (bias0 + sh[0]) * post;
}

// ---------------- fp16 tensor-core GEMM, single-barrier double-buffered pipeline ----------------
#define LDA_H 136
#define LDW_H 72
#define LDC_S 132
#define GBUF  35840

template<int MODE>
__global__ void __launch_bounds__(256, 2) gemm_h(const float* __restrict__ biasp,
                                                 const float* __restrict__ xres,
                                                 float* __restrict__ Yout) {
    extern __shared__ char smem[];
    float* BsRep = (float*)(smem + 71680);
    float* Cs    = (float*)smem;

    const __half* Ah; const __half* Wh; const float* bias;
    __half* Yh = nullptr; int ldY = 512, m0, n0;
    if (MODE == 0) {
        int b = blockIdx.x;
        if (b < 128) { m0 = (b & 31) * 128; n0 = (b >> 5) * 128;
                       Ah = g_xh; Wh = g_wqh;  bias = g_bq;  Yh = g_qth;  ldY = 512; }
        else { b -= 128; m0 = (b & 31) * 128; n0 = (b >> 5) * 128;
                       Ah = g_ch; Wh = g_wkvh; bias = g_bkv; Yh = g_kvth; ldY = 1024; }
    } else {
        m0 = blockIdx.x * 128; n0 = blockIdx.y * 128;
        Ah = g_oth; Wh = g_wph; bias = biasp;
    }

    const int tid = threadIdx.x, wid = tid >> 5;
    const int wm = (wid & 1) * 64, wn = (wid >> 1) * 32;
    const uint32_t smb = cvta_s(smem);

    const int ak = tid >> 4, am8 = (tid & 15) * 8;
    const int wnn = tid >> 3, wk8 = (tid & 7) * 8;

    auto stage = [&](int k0, int b) {
        uint32_t asb = smb + b * GBUF;
        uint32_t wsb = asb + 17408;
        #pragma unroll
        for (int i = 0; i < 4; ++i) {
            int k = ak + i * 16;
            cp16(asb + ((k * LDA_H + am8) << 1), &Ah[(k0 + k) * 4096 + m0 + am8]);
        }
        #pragma unroll
        for (int i = 0; i < 4; ++i) {
            int n = wnn + i * 32;
            cp16(wsb + ((n * LDW_H + wk8) << 1), &Wh[(n0 + n) * 512 + k0 + wk8]);
        }
    };

    stage(0, 0);
    CP_COMMIT();
    #pragma unroll
    for (int i = 0; i < 8; ++i) {
        int idx = tid + i * 256;
        BsRep[idx] = bias[n0 + (idx & 127)];
    }
    __syncthreads();        // BsRep visible

    wmma::fragment<wmma::accumulator, 16, 16, 16, float> acc[4][2];
    #pragma unroll
    for (int i = 0; i < 4; ++i)
        #pragma unroll
        for (int j = 0; j < 2; ++j)
            wmma::load_matrix_sync(acc[i][j], &BsRep[wn + j * 16], 128, wmma::mem_row_major);

    // single-barrier multistage: wait(all) -> barrier -> stage next -> compute
    for (int it = 0; it < 8; ++it) {
        int b = it & 1;
        CP_WAIT(0);
        __syncthreads();    // group-it data visible to all; compute it-1 finished by all
        if (it < 7) { stage((it + 1) * 64, b ^ 1); CP_COMMIT(); }

        __half* As = (__half*)(smem + b * GBUF);
        __half* Ws = (__half*)(smem + b * GBUF + 17408);
        #pragma unroll
        for (int ks = 0; ks < 4; ++ks) {
            wmma::fragment<wmma::matrix_a, 16, 16, 16, __half, wmma::col_major> af[4];
            wmma::fragment<wmma::matrix_b, 16, 16, 16, __half, wmma::col_major> bf[2];
            #pragma unroll
            for (int i = 0; i < 4; ++i)
                wmma::load_matrix_sync(af[i], &As[(ks * 16) * LDA_H + wm + i * 16], LDA_H);
            #pragma unroll
            for (int j = 0; j < 2; ++j)
                wmma::load_matrix_sync(bf[j], &Ws[(wn + j * 16) * LDW_H + ks * 16], LDW_H);
            #pragma unroll
            for (int i = 0; i < 4; ++i)
                #pragma unroll
                for (int j = 0; j < 2; ++j)
                    wmma::mma_sync(acc[i][j], af[i], bf[j], acc[i][j]);
        }
    }
    __syncthreads();        // all mma smem reads done before Cs alias

    if (MODE == 2) {
        #pragma unroll
        for (int i = 0; i < 4; ++i)
            #pragma unroll
            for (int j = 0; j < 2; ++j)
                wmma::store_matrix_sync(&Cs[(wn + j * 16) * LDC_S + wm + i * 16],
                                        acc[i][j], LDC_S, wmma::mem_col_major);
        __syncthreads();
        #pragma unroll
        for (int i = 0; i < 16; ++i) {
            int idx = tid + i * 256;
            int o = idx >> 5, s4 = (idx & 31) * 4;
            float4 c = *(float4*)&Cs[o * LDC_S + s4];
            float4 xv = *(const float4*)&xres[(n0 + o) * 4096 + m0 + s4];
            c.x += xv.x; c.y += xv.y; c.z += xv.z; c.w += xv.w;
            *(float4*)&Yout[(n0 + o) * 4096 + m0 + s4] = c;
        }
    } else {
        #pragma unroll
        for (int i = 0; i < 4; ++i)
            #pragma unroll
            for (int j = 0; j < 2; ++j)
                wmma::store_matrix_sync(&Cs[(wm + i * 16) * LDC_S + wn + j * 16],
                                        acc[i][j], LDC_S, wmma::mem_row_major);
        __syncthreads();
        #pragma unroll
        for (int i = 0; i < 4; ++i) {
            int idx = tid + i * 256;
            int m = idx >> 3, n16 = (idx & 7) * 16;
            const float* src = &Cs[m * LDC_S + n16];
            half2* dst = (half2*)&Yh[(m0 + m) * ldY + n0 + n16];
            #pragma unroll
            for (int q = 0; q < 8; ++q)
                dst[q] = __floats2half2_rn(src[2 * q], src[2 * q + 1]);
        }
    }
}

// ---------------- flash attention: 256-row Q tile, single-barrier KV pipeline ----------------
#define LDK 72
#define KVBUF 18432
__global__ void __launch_bounds__(256, 1) attn_p() {
    extern __shared__ char smem[];   // 2 KV buffers (36864 B), aliased as O stage at end

    const int q0 = blockIdx.x * 256;
    const int hb = blockIdx.y * 64;
    const int tid = threadIdx.x;
    const int wid = tid >> 5, lane = tid & 31;
    const int wm = wid * 32;                   // 32 q-rows per warp (2 m16 tiles)
    const int lr = lane & 7, grp = lane >> 3;
    const int gq = lane >> 2, gi = lane & 3;

    const uint32_t smb = cvta_s(smem);
    const uint32_t ksb0 = smb;                 // Ks at buf start, Vs at +9216
    const uint32_t vsb0 = smb + 9216;

    auto stage_kv = [&](int kt, int b) {
        uint32_t kb = ksb0 + b * KVBUF, vb = vsb0 + b * KVBUF;
        #pragma unroll
        for (int i = 0; i < 4; ++i) {
            int idx = tid + i * 256;
            int r = (idx & 511) >> 3, c8 = (idx & 7) * 8;
            int off = (idx < 512) ? hb : 512 + hb;
            uint32_t dst = ((idx < 512) ? kb : vb) + ((r * LDK + c8) << 1);
            cp16(dst, &g_kvth[(kt * 64 + r) * 1024 + off + c8]);
        }
    };

    stage_kv(0, 0);
    CP_COMMIT();

    // Q fragments straight from gmem into registers (held for the whole loop)
    uint32_t qf[2][4][4];
    #pragma unroll
    for (int t = 0; t < 2; ++t) {
        int r0 = q0 + wm + t * 16 + gq;
        #pragma unroll
        for (int kk = 0; kk < 4; ++kk) {
            int c0 = hb + kk * 16 + gi * 2;
            qf[t][kk][0] = *(const uint32_t*)&g_qth[r0 * 512 + c0];
            qf[t][kk][1] = *(const uint32_t*)&g_qth[(r0 + 8) * 512 + c0];
            qf[t][kk][2] = *(const uint32_t*)&g_qth[r0 * 512 + c0 + 8];
            qf[t][kk][3] = *(const uint32_t*)&g_qth[(r0 + 8) * 512 + c0 + 8];
        }
    }

    const uint32_t kB = ksb0 + (((lr + ((grp >> 1) << 3)) * LDK + ((grp & 1) << 3)) << 1);
    const uint32_t vB = vsb0 + (((lr + ((grp & 1) << 3)) * LDK + ((grp >> 1) << 3)) << 1);
    const uint32_t ONES = 0x3C003C00u;

    float oacc[2][8][4];
    float lacc[2][4];
    #pragma unroll
    for (int t = 0; t < 2; ++t) {
        #pragma unroll
        for (int j = 0; j < 8; ++j)
            #pragma unroll
            for (int e = 0; e < 4; ++e) oacc[t][j][e] = 0.f;
        #pragma unroll
        for (int e = 0; e < 4; ++e) lacc[t][e] = 0.f;
    }

    // single-barrier multistage: wait(all) -> barrier -> stage next -> compute
    for (int kt = 0; kt < 64; ++kt) {
        const int b = kt & 1;
        CP_WAIT(0);
        __syncthreads();   // tile-kt data visible; all warps finished tile kt-1
        if (kt < 63) { stage_kv(kt + 1, b ^ 1); CP_COMMIT(); }

        const uint32_t kBb = kB + b * KVBUF;
        const uint32_t vBb = vB + b * KVBUF;

        // ---- S = Q K^T : 32x64 per warp ----
        float sacc[2][8][4];
        #pragma unroll
        for (int t = 0; t < 2; ++t)
            #pragma unroll
            for (int j = 0; j < 8; ++j)
                #pragma unroll
                for (int e = 0; e < 4; ++e) sacc[t][j][e] = 0.f;

        #pragma unroll
        for (int kk = 0; kk < 4; ++kk) {
            #pragma unroll
            for (int kj = 0; kj < 4; ++kj) {
                uint32_t b0, b1, b2, b3;
                ldm_x4(b0, b1, b2, b3, kBb + ((((kj << 4) * LDK) + (kk << 4)) << 1));
                #pragma unroll
                for (int t = 0; t < 2; ++t) {
                    mma16816(sacc[t][2 * kj],     qf[t][kk][0], qf[t][kk][1],
                             qf[t][kk][2], qf[t][kk][3], b0, b1);
                    mma16816(sacc[t][2 * kj + 1], qf[t][kk][0], qf[t][kk][1],
                             qf[t][kk][2], qf[t][kk][3], b2, b3);
                }
            }
        }

        // ---- P = exp2(S) in fp16 (clamped), packed for PV ----
        uint32_t ph[2][8][2];
        #pragma unroll
        for (int t = 0; t < 2; ++t)
            #pragma unroll
            for (int j = 0; j < 8; ++j) {
                ph[t][j][0] = clamp_ex2_h2(packh2(sacc[t][j][0], sacc[t][j][1]));
                ph[t][j][1] = clamp_ex2_h2(packh2(sacc[t][j][2], sacc[t][j][3]));
            }

        // ---- O += P V (+ row sums via ones-mma) ----
        #pragma unroll
        for (int kkk = 0; kkk < 4; ++kkk) {
            #pragma unroll
            for (int jv = 0; jv < 4; ++jv) {
                uint32_t b0, b1, b2, b3;
                ldm_x4_t(b0, b1, b2, b3, vBb + ((((kkk << 4) * LDK) + (jv << 4)) << 1));
                #pragma unroll
                for (int t = 0; t < 2; ++t) {
                    uint32_t pa0 = ph[t][2 * kkk][0],     pa1 = ph[t][2 * kkk][1];
                    uint32_t pa2 = ph[t][2 * kkk + 1][0], pa3 = ph[t][2 * kkk + 1][1];
                    mma16816(oacc[t][2 * jv],     pa0, pa1, pa2, pa3, b0, b1);
                    mma16816(oacc[t][2 * jv + 1], pa0, pa1, pa2, pa3, b2, b3);
                }
            }
            #pragma unroll
            for (int t = 0; t < 2; ++t)
                mma16816(lacc[t], ph[t][2 * kkk][0], ph[t][2 * kkk][1],
                         ph[t][2 * kkk + 1][0], ph[t][2 * kkk + 1][1], ONES, ONES);
        }
    }

    // row sums exact in lacc: [t][0] = row gq sum, [t][2] = row gq+8 sum
    float i0[2], i1[2];
    #pragma unroll
    for (int t = 0; t < 2; ++t) { i0[t] = 1.f / lacc[t][0]; i1[t] = 1.f / lacc[t][2]; }

    __syncthreads();                 // all KV reads done; alias smem as O stage
    __half* Osm = (__half*)smem;     // [256][LDK] = 36864 B
    #pragma unroll
    for (int t = 0; t < 2; ++t)
        #pragma unroll
        for (int jd = 0; jd < 8; ++jd) {
            *(half2*)&Osm[(wm + t * 16 + gq) * LDK + jd * 8 + gi * 2] =
                __floats2half2_rn(oacc[t][jd][0] * i0[t], oacc[t][jd][1] * i0[t]);
            *(half2*)&Osm[(wm + t * 16 + gq + 8) * LDK + jd * 8 + gi * 2] =
                __floats2half2_rn(oacc[t][jd][2] * i1[t], oacc[t][jd][3] * i1[t]);
        }
    __syncthreads();

    // write fp16 [c][s]
    #pragma unroll
    for (int i = 0; i < 32; ++i) {
        int u = tid + i * 256;               // 8192 units
        int d = u >> 7, qp = (u & 127) * 2;
        __half va = Osm[qp * LDK + d], vb = Osm[(qp + 1) * LDK + d];
        *(half2*)&g_oth[(hb + d) * 4096 + q0 + qp] = __halves2half2(va, vb);
    }
}

// ---------------- launch ----------------
extern "C" void kernel_launch(void* const* d_in, const int* in_sizes, int n_in,
                              void* d_out, int out_size) {
    const float* x   = (const float*)d_in[0];
    const float* ctx = (const float*)d_in[1];
    const float* nwx = (const float*)d_in[2];
    const float* nbx = (const float*)d_in[3];
    const float* nwc = (const float*)d_in[4];
    const float* nbc = (const float*)d_in[5];
    const float* qw  = (const float*)d_in[6];
    const float* qb  = (const float*)d_in[7];
    const float* kvw = (const float*)d_in[8];
    const float* kvb = (const float*)d_in[9];
    const float* pw  = (const float*)d_in[10];
    const float* pb  = (const float*)d_in[11];
    float* out = (float*)d_out;

    const int GEMM_SMEM = 79872;
    const int ATTN_SMEM = 2 * KVBUF;         // 36864 B

    static bool attr_done = false;
    if (!attr_done) {
        cudaFuncSetAttribute(gemm_h<0>, cudaFuncAttributeMaxDynamicSharedMemorySize, GEMM_SMEM);
        cudaFuncSetAttribute(gemm_h<2>, cudaFuncAttributeMaxDynamicSharedMemorySize, GEMM_SMEM);
        attr_done = true;
    }

    stats_part<<<1024, 256>>>(x, ctx);
    fold_kernel<<<2048, 128>>>(qw, qb, kvw, kvb, pw, nwx, nbx, nwc, nbc);
    gemm_h<0><<<384, 256, GEMM_SMEM>>>(nullptr, nullptr, nullptr);
    attn_p<<<dim3(16, 8), 256, ATTN_SMEM>>>();
    gemm_h<2><<<dim3(32, 4), 256, GEMM_SMEM>>>(pb, x, out);
}